// round 17
// baseline (speedup 1.0000x reference)
#include <cuda_runtime.h>
#include <cuda_fp16.h>
#include <mma.h>
#include <cstdint>
#include <math.h>

using namespace nvcuda;

// Problem constants
#define TSTEPS 512
#define BATCH  512
#define IDIM   128
#define HDIM   512
#define KACT   640   // reordered: cols [0,512)=h, [512,640)=inp

// Partitioning: 8 batch-groups x 16 CTAs = 128 CTAs (1 per SM, one wave)
#define NGROUPS 8
#define GCTAS   16
#define NCTA    (NGROUPS*GCTAS)
#define MB      64
#define HS      32
#define NTHREADS 256   // 8 warps: 2 warp-rows x 4 warp-cols (32x32 tiles)

// Extended N: 128 gate cols (gate-interleaved) + 16 fc cols (8 real + 8 pad)
#define NROWS 144

// SMEM padding / tiling
#define WPAD 648      // weight row stride (halfs)
#define APAD 136      // A-stage row stride (halfs)
#define CHUNK 128     // K columns per staged chunk
#define NCHUNK 5      // 640 / 128
#define HCHUNK 4      // chunks [0,4) = h region [0,512); chunk 4 = inp [512,640)
#define F2P  18       // fcz buffer pitch (floats)

// SMEM layout (bytes):
//  Wsm  144*WPAD*2 = 186624   @ 0
//    rows 0..127: GATE-INTERLEAVED: row r -> warp block wc=r>>5 covers h-cols
//    [wc*8, wc*8+8); within block: [i(8) | f(8) | g(8) | o(8)].
//    rows 128..143: fc rows (8 real over K<512, rest zero)
//  Ast  2*64*APAD*2 = 34816   @ 186624   (gsm is GONE -- gates stay in registers)
//  fczb 64*F2P*4   = 4608     @ 221440
//  fcbs 8*4        = 32       @ 226048
#define SMEM_BYTES 226816

// Global state
__device__ __align__(16) __half g_act[2][BATCH][KACT];   // [parity][row][col]
__device__ unsigned g_bar[NGROUPS];                       // monotonic barrier counters

// ---------------- barriers (release-atomic + relaxed spin, tid0 only) ----------------
__device__ __forceinline__ void bar_arrive(const unsigned* barp) {
    if (threadIdx.x == 0) {
        asm volatile("red.release.gpu.global.add.u32 [%0], %1;"
                     :: "l"(barp), "r"(1u) : "memory");
    }
}
__device__ __forceinline__ void bar_wait(const unsigned* barp, unsigned target) {
    if (threadIdx.x == 0) {
        unsigned v;
        do {
            asm volatile("ld.relaxed.gpu.global.u32 %0, [%1];" : "=r"(v) : "l"(barp));
        } while (v < target);
        asm volatile("fence.acq_rel.gpu;" ::: "memory");
    }
    __syncthreads();
}

__device__ __forceinline__ uint4 ldcg4(const void* p) {
    return __ldcg(reinterpret_cast<const uint4*>(p));
}

// MUFU.TANH-based activations (1 MUFU/op; r16-validated)
__device__ __forceinline__ float ftanh_(float z) {
    float r;
    asm("tanh.approx.f32 %0, %1;" : "=f"(r) : "f"(z));
    return r;
}
__device__ __forceinline__ float fsigmoid(float z) {
    return fmaf(0.5f, ftanh_(0.5f * z), 0.5f);
}

// Staged-chunk MMA over chunks [c_begin, c_end). Accumulates act @ W^T.
// 8 warps: warp (wr,wc) owns rows [wr*32,+32) x interleaved cols [wc*32,+32).
// do_fc warps (wids 3,4) accumulate the 16-col fc tile with both A fragments.
// Staging: LDG(.cg)->reg->STS, 4x uint4 per thread per chunk (proven fastest).
__device__ __forceinline__ void mma_chunks(
    wmma::fragment<wmma::accumulator, 16, 16, 16, float> (&acc)[2][2],
    wmma::fragment<wmma::accumulator, 16, 16, 16, float> (&accfc)[2],
    const __half* __restrict__ gact_p,
    __half* __restrict__ Ast,            // [2 buf][64][APAD]
    const __half* __restrict__ Wsm,
    int row0, int wr, int wc, int lrow, int lseg,
    int c_begin, int c_end, bool do_fc)
{
    const __half* src = gact_p + (size_t)(row0 + lrow) * KACT + lseg*32;

    // stage chunk c_begin into buf 0 (32 halves = 4 x uint4)
    {
        const __half* s = src + c_begin*CHUNK;
        uint4 v0 = ldcg4(s);
        uint4 v1 = ldcg4(s + 8);
        uint4 v2 = ldcg4(s + 16);
        uint4 v3 = ldcg4(s + 24);
        uint4* d = reinterpret_cast<uint4*>(Ast + lrow*APAD + lseg*32);
        d[0] = v0; d[1] = v1; d[2] = v2; d[3] = v3;
    }
    __syncthreads();

    int buf = 0;
    for (int cc = c_begin; cc < c_end; cc++) {
        uint4 p0, p1, p2, p3;
        const bool hn = (cc + 1 < c_end);
        if (hn) {
            const __half* s = src + (cc+1)*CHUNK;
            p0 = ldcg4(s);
            p1 = ldcg4(s + 8);
            p2 = ldcg4(s + 16);
            p3 = ldcg4(s + 24);
        }

        const __half* Ab = Ast + buf * (64 * APAD);
        const int kbase = cc * CHUNK;
        #pragma unroll
        for (int kt = 0; kt < 8; kt++) {
            wmma::fragment<wmma::matrix_a, 16, 16, 16, __half, wmma::row_major> af[2];
            #pragma unroll
            for (int i = 0; i < 2; i++)
                wmma::load_matrix_sync(af[i], Ab + (wr*32 + i*16)*APAD + kt*16, APAD);
            #pragma unroll
            for (int j = 0; j < 2; j++) {
                wmma::fragment<wmma::matrix_b, 16, 16, 16, __half, wmma::col_major> bf;
                wmma::load_matrix_sync(bf, Wsm + (wc*32 + j*16)*WPAD + kbase + kt*16, WPAD);
                #pragma unroll
                for (int i = 0; i < 2; i++)
                    wmma::mma_sync(acc[i][j], af[i], bf, acc[i][j]);
            }
            if (do_fc) {
                wmma::fragment<wmma::matrix_b, 16, 16, 16, __half, wmma::col_major> bffc;
                wmma::load_matrix_sync(bffc, Wsm + 128*WPAD + kbase + kt*16, WPAD);
                #pragma unroll
                for (int i = 0; i < 2; i++)
                    wmma::mma_sync(accfc[i], af[i], bffc, accfc[i]);
            }
        }
        if (hn) {
            buf ^= 1;
            uint4* d = reinterpret_cast<uint4*>(Ast + buf*(64*APAD) + lrow*APAD + lseg*32);
            d[0] = p0; d[1] = p1; d[2] = p2; d[3] = p3;
        }
        __syncthreads();
    }
}

__global__ void __launch_bounds__(NTHREADS, 1)
decoder_kernel(
    const float* __restrict__ x,    const float* __restrict__ h0,
    const float* __restrict__ c0,   const float* __restrict__ W_ih,
    const float* __restrict__ W_hh, const float* __restrict__ b_ih,
    const float* __restrict__ b_hh, const float* __restrict__ fc_W,
    const float* __restrict__ fc_b, float* __restrict__ out)
{
    extern __shared__ unsigned char smem_raw[];
    __half* Wsm  = (__half*)smem_raw;                        // [144][WPAD]
    __half* Ast  = (__half*)(smem_raw + 186624);             // [2][64][APAD]
    float*  fczb = (float*)(smem_raw + 221440);              // [64][F2P]
    float*  fcbs = (float*)(smem_raw + 226048);              // [8]

    const int tid  = threadIdx.x;
    const int gid  = blockIdx.x / GCTAS;
    const int rk   = blockIdx.x % GCTAS;
    const int row0 = gid * MB;
    const int hs   = rk * HS;
    const unsigned* barp = &g_bar[gid];

    const int wid  = tid >> 5;
    const int lane = tid & 31;
    const int wr  = wid >> 2;        // 0..1 : 32 rows (batch m) each
    const int wc  = wid & 3;         // 0..3 : h-cols [wc*8, wc*8+8) x 4 gates
    const int lrow = tid >> 2;       // 0..63
    const int lseg = tid & 3;        // 0..3
    // fc tile carried by wids 3 (SMSP3, wr=0) and 4 (SMSP0, wr=1) -- r10-proven
    const bool fcw = (wid == 3) || (wid == 4);

    // HMMA.16816 accumulator geometry for this lane
    const int arow = lane >> 2;          // base row within 16-row frag
    const int jj0  = 2 * (lane & 3);     // base col-pair within 8-col gate band

    // ---------------- init (once) ----------------
    // Wsm rows 0..127: gate-INTERLEAVED. Row r: wcb=r>>5, w=r&31, gate q=w>>3,
    // jj=w&7 -> h-col = wcb*8+jj; K-reordered (k<512 -> W_hh, k>=512 -> W_ih).
    // Wsm rows 128..143: fc rows (8 real over K<512, rest zero).
    for (int idx = tid; idx < NROWS*KACT; idx += NTHREADS) {
        int r = idx / KACT, k = idx - r*KACT;
        float v;
        if (r < 128) {
            int wcb = r >> 5, w = r & 31;
            int q = w >> 3, jj = w & 7;
            int grow = q*HDIM + hs + wcb*8 + jj;
            v = (k < HDIM) ? W_hh[grow*HDIM + k] : W_ih[grow*IDIM + (k - HDIM)];
        } else {
            int ff = r - 128;
            v = (ff < 8 && k < HDIM) ? fc_W[(rk*8 + ff)*HDIM + k] : 0.0f;
        }
        Wsm[r*WPAD + k] = __float2half_rn(v);
    }
    if (tid < 8) fcbs[tid] = fc_b[rk*8 + tid];

    // Per-thread gate biases: bz[gate][p] for h-cols hs + wc*8 + jj0 + p
    float bz[4][2];
    #pragma unroll
    for (int g = 0; g < 4; g++)
        #pragma unroll
        for (int p = 0; p < 2; p++) {
            int col = g*HDIM + hs + wc*8 + jj0 + p;
            bz[g][p] = b_ih[col] + b_hh[col];
        }

    // cell state in registers, acc-fragment mapping:
    // cell (i, rh, p): row m = wr*32 + i*16 + arow + 8*rh; h-col j = wc*8 + jj0 + p
    float cr[8];
    #pragma unroll
    for (int i = 0; i < 2; i++)
        #pragma unroll
        for (int rh = 0; rh < 2; rh++)
            #pragma unroll
            for (int p = 0; p < 2; p++) {
                int m = wr*32 + i*16 + arow + 8*rh;
                int j = wc*8 + jj0 + p;
                cr[i*4 + rh*2 + p] = c0[(row0+m)*HDIM + hs + j];
            }

    // seed g_act parity 0: h at cols [hs,hs+32), inp at cols [512+rk*8,+8)
    for (int idx = tid; idx < MB*HS; idx += NTHREADS) {
        int m = idx >> 5, j = idx & 31;
        g_act[0][row0+m][hs+j] = __float2half_rn(h0[(row0+m)*HDIM + hs + j]);
    }
    for (int idx = tid; idx < MB*8; idx += NTHREADS) {
        int m = idx >> 3, ccol = rk*8 + (idx & 7);
        g_act[0][row0+m][HDIM+ccol] =
            __float2half_rn(x[(TSTEPS-1)*BATCH*IDIM + (row0+m)*IDIM + ccol]);
    }

    __syncthreads();              // all seed writes done before arrive
    bar_arrive(barp);
    unsigned tgt = GCTAS;
    bar_wait(barp, tgt);          // seeds visible group-wide

    wmma::fragment<wmma::accumulator, 16, 16, 16, float> acc[2][2];
    wmma::fragment<wmma::accumulator, 16, 16, 16, float> accfc[2];

    // ---------------- prologue: gates(0) -> acc (registers; no publish) ----------------
    {
        #pragma unroll
        for (int i = 0; i < 2; i++)
            #pragma unroll
            for (int j = 0; j < 2; j++)
                wmma::fill_fragment(acc[i][j], 0.0f);
        mma_chunks(acc, accfc, &g_act[0][0][0], Ast, Wsm, row0, wr, wc, lrow, lseg,
                   0, NCHUNK, false);
    }

    // ---------------- 512 sequential steps ----------------
    for (int t = 0; t < TSTEPS; t++) {
        const int pw = (t + 1) & 1;      // parity holding h_{t+1} / inp_{t+1}
        const bool more = (t < TSTEPS - 1);

        // ===== pointwise LSTM on REGISTER-RESIDENT gates (acc = gates_t) =====
        // acc[i][0].x: cols 0..7 = gate i, 8..15 = gate f (this warp's 8 h-cols)
        // acc[i][1].x: cols 0..7 = gate g, 8..15 = gate o
        // x[e]: e = rh*2 + p -> (row arow+8*rh, col jj0+p); x[e+4] = col +8.
        #pragma unroll
        for (int i = 0; i < 2; i++) {
            #pragma unroll
            for (int rh = 0; rh < 2; rh++) {
                float hn2[2];
                #pragma unroll
                for (int p = 0; p < 2; p++) {
                    const int e = rh*2 + p;
                    const int c = i*4 + rh*2 + p;
                    float zi = acc[i][0].x[e]   + bz[0][p];
                    float zf = acc[i][0].x[e+4] + bz[1][p];
                    float zg = acc[i][1].x[e]   + bz[2][p];
                    float zo = acc[i][1].x[e+4] + bz[3][p];
                    float ig = fsigmoid(zi);
                    float fg = fsigmoid(zf);
                    float gg = ftanh_(zg);
                    float og = fsigmoid(zo);
                    float cn = fg*cr[c] + ig*gg;
                    float hnv = og * ftanh_(cn);
                    cr[c] = cn;
                    hn2[p] = hnv;
                }
                int m = wr*32 + i*16 + arow + 8*rh;
                *reinterpret_cast<__half2*>(&g_act[pw][row0+m][hs + wc*8 + jj0]) =
                    __floats2half2_rn(hn2[0], hn2[1]);
            }
        }
        __syncthreads();                 // all h writes done before arrive
        bar_arrive(barp);                // A: h_{t+1} published
        tgt += GCTAS;
        bar_wait(barp, tgt);

        // ===== phase1: gates(t+1) h-part + FULL fcz_t (fc on wids 3,4) =====
        #pragma unroll
        for (int i = 0; i < 2; i++) {
            wmma::fill_fragment(accfc[i], 0.0f);
            #pragma unroll
            for (int j = 0; j < 2; j++)
                wmma::fill_fragment(acc[i][j], 0.0f);
        }
        mma_chunks(acc, accfc, &g_act[pw][0][0], Ast, Wsm, row0, wr, wc, lrow, lseg,
                   0, HCHUNK, fcw);
        if (fcw) {
            #pragma unroll
            for (int i = 0; i < 2; i++)
                wmma::store_matrix_sync(&fczb[(wr*32 + i*16)*F2P], accfc[i],
                                        F2P, wmma::mem_row_major);
        }
        __syncthreads();

        // ===== finalize: out_t = tanh(0.5*(fcz+b)); feedback inp_{t+1} =====
        float yv[2]; int mv[2], nv[2];
        #pragma unroll
        for (int it = 0; it < 2; it++) {
            int idx = tid + it*NTHREADS;
            int m = idx >> 3, ff = idx & 7;
            float z = fczb[m*F2P + ff] + fcbs[ff];
            float y = ftanh_(0.5f * z);  // == 2*sigmoid(z) - 1
            g_act[pw][row0+m][HDIM + rk*8 + ff] = __float2half_rn(y);
            yv[it] = y; mv[it] = m; nv[it] = rk*8 + ff;
        }
        __syncthreads();                 // all inp writes done before arrive
        if (more) { bar_arrive(barp); tgt += GCTAS; }   // B: inp published

        // out stores overlap the barrier-B window
        #pragma unroll
        for (int it = 0; it < 2; it++)
            out[(TSTEPS-1-t)*BATCH*IDIM + (row0+mv[it])*IDIM + nv[it]] = yv[it];

        if (more) {
            bar_wait(barp, tgt);         // B
            // ===== phase2: gates(t+1) inp-part; acc stays in registers =====
            mma_chunks(acc, accfc, &g_act[pw][0][0], Ast, Wsm, row0, wr, wc, lrow, lseg,
                       HCHUNK, NCHUNK, false);
        }
    }
}

extern "C" void kernel_launch(void* const* d_in, const int* in_sizes, int n_in,
                              void* d_out, int out_size)
{
    const float* x    = (const float*)d_in[0];
    // d_in[1] = enc_hiddens : unused by the reference recursion
    const float* h0   = (const float*)d_in[2];
    const float* c0   = (const float*)d_in[3];
    const float* W_ih = (const float*)d_in[4];
    const float* W_hh = (const float*)d_in[5];
    const float* b_ih = (const float*)d_in[6];
    const float* b_hh = (const float*)d_in[7];
    const float* fc_W = (const float*)d_in[8];
    const float* fc_b = (const float*)d_in[9];
    float* out = (float*)d_out;

    cudaFuncSetAttribute(decoder_kernel, cudaFuncAttributeMaxDynamicSharedMemorySize, SMEM_BYTES);

    // Reset group-barrier counters every replay (captured memset node)
    void* barp = nullptr;
    cudaGetSymbolAddress(&barp, g_bar);
    cudaMemsetAsync(barp, 0, sizeof(unsigned) * NGROUPS);

    decoder_kernel<<<NCTA, NTHREADS, SMEM_BYTES>>>(x, h0, c0, W_ih, W_hh,
                                                   b_ih, b_hh, fc_W, fc_b, out);
}